// round 3
// baseline (speedup 1.0000x reference)
#include <cuda_runtime.h>
#include <cuda_bf16.h>

// Seesaw loss, collapsed form:
//   denom[b] = sum_{j != t} s[t,j]*exp(l[b,j]) + exp(l[b,t])
//   loss[b]  = -log( exp(l[b,t]) / (denom + eps) + eps )
//   out      = mean_b loss[b]
// Shift-invariance of sigma makes the row-max subtraction unnecessary
// (eps enters at >= 1e-6 relative in either scaling; logits are O(1)).

#define C_CLASSES 1604
#define C_VEC (C_CLASSES / 4)   // 401 float4 per row
#define B_MAX 16384
#define WARPS_PER_BLOCK 8
#define EPS 1e-6f

__device__ float g_partial[B_MAX];

__global__ __launch_bounds__(WARPS_PER_BLOCK * 32)
void seesaw_row_kernel(const float* __restrict__ logits,
                       const float* __restrict__ s,
                       const int* __restrict__ targets,
                       int B) {
    const int warp = threadIdx.x >> 5;
    const int lane = threadIdx.x & 31;
    const int b = blockIdx.x * WARPS_PER_BLOCK + warp;
    if (b >= B) return;

    const int t = targets[b];
    const float4* __restrict__ lrow = (const float4*)(logits + (size_t)b * C_CLASSES);
    const float4* __restrict__ wrow = (const float4*)(s + (size_t)t * C_CLASSES);

    float acc = 0.0f;
    #pragma unroll 4
    for (int v = lane; v < C_VEC; v += 32) {
        float4 l = lrow[v];
        float4 w = wrow[v];
        acc = fmaf(w.x, __expf(l.x), acc);
        acc = fmaf(w.y, __expf(l.y), acc);
        acc = fmaf(w.z, __expf(l.z), acc);
        acc = fmaf(w.w, __expf(l.w), acc);
    }

    // warp tree-reduce
    #pragma unroll
    for (int off = 16; off > 0; off >>= 1)
        acc += __shfl_xor_sync(0xFFFFFFFFu, acc, off);

    if (lane == 0) {
        float lt  = logits[(size_t)b * C_CLASSES + t];
        float et  = __expf(lt);
        float wtt = s[(size_t)t * C_CLASSES + t];
        // remove the j==t term of the weighted sum, add plain exp(l_t)
        float denom = acc - wtt * et + et;
        float sigma = et / (denom + EPS);
        g_partial[b] = -logf(sigma + EPS);
    }
}

__global__ __launch_bounds__(256)
void seesaw_reduce_kernel(float* __restrict__ out, int B) {
    __shared__ float sh[256];
    float acc = 0.0f;
    for (int i = threadIdx.x; i < B; i += 256)
        acc += g_partial[i];
    sh[threadIdx.x] = acc;
    __syncthreads();
    #pragma unroll
    for (int stride = 128; stride > 0; stride >>= 1) {
        if (threadIdx.x < stride) sh[threadIdx.x] += sh[threadIdx.x + stride];
        __syncthreads();
    }
    if (threadIdx.x == 0)
        out[0] = sh[0] / (float)B;
}

extern "C" void kernel_launch(void* const* d_in, const int* in_sizes, int n_in,
                              void* d_out, int out_size) {
    const float* logits  = (const float*)d_in[0];   // [B, C] f32
    const float* s       = (const float*)d_in[1];   // [C, C] f32
    const int*   targets = (const int*)d_in[2];     // [B] int32
    float* out = (float*)d_out;

    const int B = in_sizes[2];

    const int rows_per_block = WARPS_PER_BLOCK;
    const int grid = (B + rows_per_block - 1) / rows_per_block;
    seesaw_row_kernel<<<grid, rows_per_block * 32>>>(logits, s, targets, B);
    seesaw_reduce_kernel<<<1, 256>>>(out, B);
}